// round 7
// baseline (speedup 1.0000x reference)
#include <cuda_runtime.h>

#define F_IN 1433
#define F1   16
#define F2   7
#define NMAX 50000

// ---------------- scratch (no allocations allowed) ----------------
__device__ __align__(16) float g_deg [NMAX];
__device__ __align__(16) float g_dinv[NMAX];
__device__ __align__(16) float g_hs1 [NMAX * 16];   // h1 * dinv (gather source, layer 1)
__device__ __align__(16) float g_agg1[NMAX * 16];   // scatter accumulator (init = self-loop term)
__device__ __align__(16) float g_hs2 [NMAX * 8];    // h2 * dinv (padded to 8)
__device__ __align__(16) float g_agg2[NMAX * 8];

// packed fp32x2 FMA (Blackwell; only reachable via PTX)
#define FMA2(d,a,b,c) asm("fma.rn.f32x2 %0, %1, %2, %3;" : "=l"(d) : "l"(a), "l"(b), "l"(c))

// ---------------- degree ----------------
__global__ void k_init(int n) {
    int i = blockIdx.x * blockDim.x + threadIdx.x;
    if (i < n) g_deg[i] = 1.0f;   // self-loop contributes 1 to every degree
}

__global__ __launch_bounds__(256) void k_deg(const int* __restrict__ ei, int E) {
    int e = blockIdx.x * blockDim.x + threadIdx.x;
    if (e < E) atomicAdd(&g_deg[ei[E + e]], 1.0f);
}

// ---------------- GEMM1: hs1 = (x @ W1) * dinv; agg1 = hs1 (self loop); dinv cached ----------------
#define RT   384      // rows per block  -> grid = 131 (single wave on 148 SMs)
#define KT   32       // k-tile
#define KPAD 1440     // F_IN padded to KT multiple
#define RPL  3        // rows per lane (W-broadcast reuse)

__global__ __launch_bounds__(128, 1) void k_gemm1(const float* __restrict__ x,
                                                  const float* __restrict__ W1, int n)
{
    extern __shared__ float sm[];
    float* w1s = sm;                   // [KPAD][16]  (92160 B)
    float* xs  = sm + KPAD * F1;       // [KT][RT+1]  (49280 B)
    const int tid  = threadIdx.x;
    const int lane = tid & 31;
    const int wid  = tid >> 5;

    for (int i = tid; i < KPAD * F1; i += 128)
        w1s[i] = (i < F_IN * F1) ? W1[i] : 0.0f;

    const int row0  = blockIdx.x * RT;
    const int rbase = wid * (32 * RPL);    // each warp owns 96 rows

    unsigned long long acc[RPL][8];
    #pragma unroll
    for (int r = 0; r < RPL; ++r)
        #pragma unroll
        for (int j = 0; j < 8; ++j) acc[r][j] = 0ULL;

    for (int k0 = 0; k0 < F_IN; k0 += KT) {
        __syncthreads();
        // stage x tile transposed: xs[k][row]  (conflict-free: 385-word row stride)
        #pragma unroll 8
        for (int p = 0; p < RT / 4; ++p) {
            int rl = p * 4 + wid;
            int gr = row0 + rl;
            int gk = k0 + lane;
            float v = 0.0f;
            if (gr < n && gk < F_IN) v = x[(size_t)gr * F_IN + gk];
            xs[lane * (RT + 1) + rl] = v;
        }
        __syncthreads();
        #pragma unroll
        for (int k = 0; k < KT; ++k) {
            const ulonglong2* wp = (const ulonglong2*)(w1s + (k0 + k) * F1);
            ulonglong2 wa = wp[0], wb = wp[1], wc = wp[2], wd = wp[3];  // broadcast LDS.128
            #pragma unroll
            for (int r = 0; r < RPL; ++r) {
                float xv = xs[k * (RT + 1) + rbase + r * 32 + lane];
                unsigned long long xx;
                asm("mov.b64 %0, {%1, %1};" : "=l"(xx) : "f"(xv));
                FMA2(acc[r][0], wa.x, xx, acc[r][0]);
                FMA2(acc[r][1], wa.y, xx, acc[r][1]);
                FMA2(acc[r][2], wb.x, xx, acc[r][2]);
                FMA2(acc[r][3], wb.y, xx, acc[r][3]);
                FMA2(acc[r][4], wc.x, xx, acc[r][4]);
                FMA2(acc[r][5], wc.y, xx, acc[r][5]);
                FMA2(acc[r][6], wd.x, xx, acc[r][6]);
                FMA2(acc[r][7], wd.y, xx, acc[r][7]);
            }
        }
    }

    #pragma unroll
    for (int r = 0; r < RPL; ++r) {
        int row = row0 + rbase + r * 32 + lane;
        if (row < n) {
            float di = rsqrtf(g_deg[row]);
            g_dinv[row] = di;
            float4 o[4];
            float* of = (float*)o;
            #pragma unroll
            for (int j = 0; j < 8; ++j) {
                union { unsigned long long u; float2 f; } cv;
                cv.u = acc[r][j];
                of[2 * j]     = cv.f.x * di;
                of[2 * j + 1] = cv.f.y * di;
            }
            float4* hp = (float4*)(g_hs1  + (size_t)row * 16);
            float4* ap = (float4*)(g_agg1 + (size_t)row * 16);
            hp[0] = o[0]; hp[1] = o[1]; hp[2] = o[2]; hp[3] = o[3];
            ap[0] = o[0]; ap[1] = o[1]; ap[2] = o[2]; ap[3] = o[3];
        }
    }
}

// ---------------- edge scatter, layer 1 (16 floats) ----------------
__global__ __launch_bounds__(256) void k_scat16(const int* __restrict__ ei, int E) {
    int e = blockIdx.x * blockDim.x + threadIdx.x;
    if (e >= E) return;
    int s = ei[e];
    int d = ei[E + e];
    const float4* hp = (const float4*)(g_hs1 + (size_t)s * 16);
    float4 v0 = hp[0], v1 = hp[1], v2 = hp[2], v3 = hp[3];
    float* dp = g_agg1 + (size_t)d * 16;
    atomicAdd(dp + 0,  v0.x); atomicAdd(dp + 1,  v0.y);
    atomicAdd(dp + 2,  v0.z); atomicAdd(dp + 3,  v0.w);
    atomicAdd(dp + 4,  v1.x); atomicAdd(dp + 5,  v1.y);
    atomicAdd(dp + 6,  v1.z); atomicAdd(dp + 7,  v1.w);
    atomicAdd(dp + 8,  v2.x); atomicAdd(dp + 9,  v2.y);
    atomicAdd(dp + 10, v2.z); atomicAdd(dp + 11, v2.w);
    atomicAdd(dp + 12, v3.x); atomicAdd(dp + 13, v3.y);
    atomicAdd(dp + 14, v3.z); atomicAdd(dp + 15, v3.w);
}

// ---------------- layer 2: relu(dinv*agg1 + b1) @ W2, prescale, self-loop init ----------------
__global__ __launch_bounds__(256) void k_layer2(const float* __restrict__ b1,
                                                const float* __restrict__ W2, int n)
{
    __shared__ float w2s[F1 * F2];
    __shared__ float b1s[F1];
    int tid = threadIdx.x;
    if (tid < F1 * F2) w2s[tid] = W2[tid];
    if (tid < F1)      b1s[tid] = b1[tid];
    __syncthreads();
    int r = blockIdx.x * blockDim.x + tid;
    if (r >= n) return;
    float di = g_dinv[r];
    const float4* ap = (const float4*)(g_agg1 + (size_t)r * 16);
    float4 A[4] = {ap[0], ap[1], ap[2], ap[3]};
    const float* a = (const float*)A;
    float h[F2];
    #pragma unroll
    for (int k = 0; k < F2; ++k) h[k] = 0.0f;
    #pragma unroll
    for (int j = 0; j < F1; ++j) {
        float aj = fmaxf(fmaf(di, a[j], b1s[j]), 0.0f);   // + b1, ReLU
        #pragma unroll
        for (int k = 0; k < F2; ++k) h[k] = fmaf(aj, w2s[j * F2 + k], h[k]);
    }
    float4 o0 = make_float4(h[0] * di, h[1] * di, h[2] * di, h[3] * di);
    float4 o1 = make_float4(h[4] * di, h[5] * di, h[6] * di, 0.0f);
    float4* hp = (float4*)(g_hs2  + (size_t)r * 8);
    float4* gp = (float4*)(g_agg2 + (size_t)r * 8);
    hp[0] = o0; hp[1] = o1;
    gp[0] = o0; gp[1] = o1;
}

// ---------------- edge scatter, layer 2 (7 floats) ----------------
__global__ __launch_bounds__(256) void k_scat8(const int* __restrict__ ei, int E) {
    int e = blockIdx.x * blockDim.x + threadIdx.x;
    if (e >= E) return;
    int s = ei[e];
    int d = ei[E + e];
    const float4* hp = (const float4*)(g_hs2 + (size_t)s * 8);
    float4 v0 = hp[0], v1 = hp[1];
    float* dp = g_agg2 + (size_t)d * 8;
    atomicAdd(dp + 0, v0.x); atomicAdd(dp + 1, v0.y);
    atomicAdd(dp + 2, v0.z); atomicAdd(dp + 3, v0.w);
    atomicAdd(dp + 4, v1.x); atomicAdd(dp + 5, v1.y);
    atomicAdd(dp + 6, v1.z);
}

// ---------------- final: + b2, log_softmax ----------------
__global__ __launch_bounds__(256) void k_final(const float* __restrict__ b2,
                                               float* __restrict__ out, int n)
{
    int r = blockIdx.x * blockDim.x + threadIdx.x;
    if (r >= n) return;
    float di = g_dinv[r];
    const float4* ap = (const float4*)(g_agg2 + (size_t)r * 8);
    float4 v0 = ap[0], v1 = ap[1];
    float v[7] = {v0.x, v0.y, v0.z, v0.w, v1.x, v1.y, v1.z};
    #pragma unroll
    for (int k = 0; k < 7; ++k) v[k] = fmaf(di, v[k], __ldg(b2 + k));
    float m = v[0];
    #pragma unroll
    for (int k = 1; k < 7; ++k) m = fmaxf(m, v[k]);
    float s = 0.0f;
    #pragma unroll
    for (int k = 0; k < 7; ++k) s += expf(v[k] - m);
    float l = m + logf(s);
    #pragma unroll
    for (int k = 0; k < 7; ++k) out[(size_t)r * 7 + k] = v[k] - l;
}

// ---------------- launch ----------------
extern "C" void kernel_launch(void* const* d_in, const int* in_sizes, int n_in,
                              void* d_out, int out_size)
{
    const float* x  = (const float*)d_in[0];
    const int*   ei = (const int*)d_in[1];     // JAX default: int32 (x64 disabled)
    const float* W1 = (const float*)d_in[2];
    const float* b1 = (const float*)d_in[3];
    const float* W2 = (const float*)d_in[4];
    const float* b2 = (const float*)d_in[5];

    int n = in_sizes[0] / F_IN;   // 50000
    int E = in_sizes[1] / 2;      // 1600000

    const int smem = (KPAD * F1 + KT * (RT + 1)) * (int)sizeof(float);  // 141440 B
    cudaFuncSetAttribute(k_gemm1, cudaFuncAttributeMaxDynamicSharedMemorySize, smem);

    k_init  <<<(n + 255) / 256, 256>>>(n);
    k_deg   <<<(E + 255) / 256, 256>>>(ei, E);
    k_gemm1 <<<(n + RT - 1) / RT, 128, smem>>>(x, W1, n);
    k_scat16<<<(E + 255) / 256, 256>>>(ei, E);
    k_layer2<<<(n + 255) / 256, 256>>>(b1, W2, n);
    k_scat8 <<<(E + 255) / 256, 256>>>(ei, E);
    k_final <<<(n + 255) / 256, 256>>>(b2, (float*)d_out, n);
}

// round 8
// speedup vs baseline: 2.6246x; 2.6246x over previous
#include <cuda_runtime.h>

#define F_IN 1433
#define F1   16
#define F2   7
#define NMAX 50000
#define EMAX 1664000
#define KPAD 1440

// ---------------- scratch (no allocations allowed) ----------------
__device__ __align__(16) int   g_cnt [NMAX];     // in-degree (real edges)
__device__ __align__(16) int   g_off [NMAX];     // CSR bucket start
__device__ __align__(16) int   g_cur [NMAX];     // fill cursor
__device__             int     g_total;          // bucket allocator
__device__ __align__(16) int   g_srcs[EMAX];     // CSR: src per in-edge, bucketed by dst
__device__ __align__(16) float g_dinv[NMAX];
__device__ __align__(16) float g_hs1 [NMAX * 16];  // (x@W1)*dinv  (gather source L1)
__device__ __align__(16) float g_a1  [NMAX * 16];  // relu(dinv*agg1 + b1)
__device__ __align__(16) float g_hs2 [NMAX * 8];   // (a1@W2)*dinv (gather source L2, col7=0)

// packed fp32x2 FMA (Blackwell; only reachable via PTX)
#define FMA2(d,a,b,c) asm("fma.rn.f32x2 %0, %1, %2, %3;" : "=l"(d) : "l"(a), "l"(b), "l"(c))

// ---------------- CSR build ----------------
__global__ void k_init(int n) {
    int i = blockIdx.x * blockDim.x + threadIdx.x;
    if (i < n) g_cnt[i] = 0;
    if (i == 0) g_total = 0;
}

__global__ __launch_bounds__(256) void k_count(const int* __restrict__ ei, int E) {
    int e = blockIdx.x * blockDim.x + threadIdx.x;
    if (e < E) atomicAdd(&g_cnt[ei[E + e]], 1);
}

// bucket offsets via warp scan + one global atomic (order of buckets irrelevant)
__global__ __launch_bounds__(256) void k_alloc(int n) {
    int i    = blockIdx.x * blockDim.x + threadIdx.x;
    int lane = threadIdx.x & 31;
    int c    = (i < n) ? g_cnt[i] : 0;
    int incl = c;
    #pragma unroll
    for (int o = 1; o < 32; o <<= 1) {
        int v = __shfl_up_sync(0xffffffffu, incl, o);
        if (lane >= o) incl += v;
    }
    int tot  = __shfl_sync(0xffffffffu, incl, 31);
    int base = 0;
    if (lane == 31) base = atomicAdd(&g_total, tot);
    base = __shfl_sync(0xffffffffu, base, 31);
    if (i < n) {
        int off = base + incl - c;
        g_off[i] = off;
        g_cur[i] = off;
        g_dinv[i] = rsqrtf((float)(c + 1));   // +1 self loop
    }
}

__global__ __launch_bounds__(256) void k_fill(const int* __restrict__ ei, int E) {
    int e = blockIdx.x * blockDim.x + threadIdx.x;
    if (e >= E) return;
    int s = ei[e];
    int d = ei[E + e];
    int p = atomicAdd(&g_cur[d], 1);
    g_srcs[p] = s;
}

// ---------------- GEMM1: hs1 = (x @ W1) * dinv ----------------
// thread-per-row, W1 in shared (broadcast LDS), x streamed from DRAM.
#define G1_BLK  192
#define G1_GRID 296                       // 2 blocks/SM exactly
#define G1_ROWS 169                       // ceil(50000/296)

__global__ __launch_bounds__(G1_BLK) void k_gemm1(const float* __restrict__ x,
                                                  const float* __restrict__ W1, int n)
{
    extern __shared__ float w1s[];        // [KPAD][16] zero-padded
    int tid = threadIdx.x;
    for (int i = tid; i < KPAD * F1; i += G1_BLK)
        w1s[i] = (i < F_IN * F1) ? W1[i] : 0.0f;
    __syncthreads();

    int row = blockIdx.x * G1_ROWS + tid;
    if (tid >= G1_ROWS || row >= n) return;
    const float* xr = x + (size_t)row * F_IN;

    unsigned long long acc[8];
    #pragma unroll
    for (int j = 0; j < 8; ++j) acc[j] = 0ULL;

    for (int k0 = 0; k0 < F_IN; k0 += 16) {
        float xb[16];
        #pragma unroll
        for (int u = 0; u < 16; ++u) {
            int k = k0 + u;
            xb[u] = (k < F_IN) ? xr[k] : 0.0f;
        }
        #pragma unroll
        for (int u = 0; u < 16; ++u) {
            unsigned long long xx;
            asm("mov.b64 %0, {%1, %1};" : "=l"(xx) : "f"(xb[u]));
            const ulonglong2* wp = (const ulonglong2*)(w1s + (k0 + u) * F1);
            ulonglong2 wa = wp[0], wb = wp[1], wc = wp[2], wd = wp[3];
            FMA2(acc[0], wa.x, xx, acc[0]);
            FMA2(acc[1], wa.y, xx, acc[1]);
            FMA2(acc[2], wb.x, xx, acc[2]);
            FMA2(acc[3], wb.y, xx, acc[3]);
            FMA2(acc[4], wc.x, xx, acc[4]);
            FMA2(acc[5], wc.y, xx, acc[5]);
            FMA2(acc[6], wd.x, xx, acc[6]);
            FMA2(acc[7], wd.y, xx, acc[7]);
        }
    }

    float di = g_dinv[row];
    float4* hp = (float4*)(g_hs1 + (size_t)row * 16);
    #pragma unroll
    for (int q = 0; q < 4; ++q) {
        union { unsigned long long u; float2 f; } a, b;
        a.u = acc[2 * q]; b.u = acc[2 * q + 1];
        hp[q] = make_float4(a.f.x * di, a.f.y * di, b.f.x * di, b.f.y * di);
    }
}

// ---------------- gather L1: a1 = relu(dinv*(self + sum_in hs1[src]) + b1) ----------------
// warp per node; 8 edge-groups x 4 lanes (float4 column each)
__global__ __launch_bounds__(256) void k_gather16(const float* __restrict__ b1, int n) {
    int wid  = threadIdx.x >> 5;
    int lane = threadIdx.x & 31;
    int d    = blockIdx.x * 8 + wid;
    if (d >= n) return;

    int base = g_off[d];
    int cnt  = g_cnt[d];
    int grp  = lane >> 2;
    int col  = lane & 3;

    float4 acc = make_float4(0.f, 0.f, 0.f, 0.f);
    for (int it = grp; it < cnt; it += 8) {
        int s = g_srcs[base + it];
        float4 v = ((const float4*)(g_hs1 + (size_t)s * 16))[col];
        acc.x += v.x; acc.y += v.y; acc.z += v.z; acc.w += v.w;
    }
    __syncwarp();
    #pragma unroll
    for (int o = 16; o >= 4; o >>= 1) {
        acc.x += __shfl_down_sync(0xffffffffu, acc.x, o);
        acc.y += __shfl_down_sync(0xffffffffu, acc.y, o);
        acc.z += __shfl_down_sync(0xffffffffu, acc.z, o);
        acc.w += __shfl_down_sync(0xffffffffu, acc.w, o);
    }
    if (lane < 4) {
        float4 self = ((const float4*)(g_hs1 + (size_t)d * 16))[lane];
        float  di   = g_dinv[d];
        float4 b    = __ldg((const float4*)b1 + lane);
        float4 o;
        o.x = fmaxf(fmaf(di, acc.x + self.x, b.x), 0.f);
        o.y = fmaxf(fmaf(di, acc.y + self.y, b.y), 0.f);
        o.z = fmaxf(fmaf(di, acc.z + self.z, b.z), 0.f);
        o.w = fmaxf(fmaf(di, acc.w + self.w, b.w), 0.f);
        ((float4*)(g_a1 + (size_t)d * 16))[lane] = o;
    }
}

// ---------------- layer 2 dense: hs2 = (a1 @ W2) * dinv  (col 7 = 0 pad) ----------------
__global__ __launch_bounds__(256) void k_layer2(const float* __restrict__ W2, int n) {
    __shared__ float w2s[F1 * F2];
    int tid = threadIdx.x;
    if (tid < F1 * F2) w2s[tid] = W2[tid];
    __syncthreads();
    int r = blockIdx.x * blockDim.x + tid;
    if (r >= n) return;
    float di = g_dinv[r];
    const float4* ap = (const float4*)(g_a1 + (size_t)r * 16);
    float4 A[4] = {ap[0], ap[1], ap[2], ap[3]};
    const float* a = (const float*)A;
    float h[F2];
    #pragma unroll
    for (int k = 0; k < F2; ++k) h[k] = 0.f;
    #pragma unroll
    for (int j = 0; j < F1; ++j) {
        float aj = a[j];
        #pragma unroll
        for (int k = 0; k < F2; ++k) h[k] = fmaf(aj, w2s[j * F2 + k], h[k]);
    }
    float4* hp = (float4*)(g_hs2 + (size_t)r * 8);
    hp[0] = make_float4(h[0] * di, h[1] * di, h[2] * di, h[3] * di);
    hp[1] = make_float4(h[4] * di, h[5] * di, h[6] * di, 0.f);
}

// ---------------- gather L2 + bias + log_softmax (fused) ----------------
// warp per node; 16 edge-groups x 2 lanes (float4 half-row each)
__global__ __launch_bounds__(256) void k_gather8f(const float* __restrict__ b2,
                                                  float* __restrict__ out, int n) {
    int wid  = threadIdx.x >> 5;
    int lane = threadIdx.x & 31;
    int d    = blockIdx.x * 8 + wid;
    if (d >= n) return;

    int base = g_off[d];
    int cnt  = g_cnt[d];
    int grp  = lane >> 1;
    int half = lane & 1;

    float4 acc = make_float4(0.f, 0.f, 0.f, 0.f);
    for (int it = grp; it < cnt; it += 16) {
        int s = g_srcs[base + it];
        float4 v = ((const float4*)(g_hs2 + (size_t)s * 8))[half];
        acc.x += v.x; acc.y += v.y; acc.z += v.z; acc.w += v.w;
    }
    __syncwarp();
    #pragma unroll
    for (int o = 16; o >= 2; o >>= 1) {
        acc.x += __shfl_down_sync(0xffffffffu, acc.x, o);
        acc.y += __shfl_down_sync(0xffffffffu, acc.y, o);
        acc.z += __shfl_down_sync(0xffffffffu, acc.z, o);
        acc.w += __shfl_down_sync(0xffffffffu, acc.w, o);
    }
    // lanes 0,1 hold the two half-row sums; add self term
    if (lane < 2) {
        float4 self = ((const float4*)(g_hs2 + (size_t)d * 8))[lane];
        acc.x += self.x; acc.y += self.y; acc.z += self.z; acc.w += self.w;
    }
    float hx = __shfl_sync(0xffffffffu, acc.x, 1);
    float hy = __shfl_sync(0xffffffffu, acc.y, 1);
    float hz = __shfl_sync(0xffffffffu, acc.z, 1);
    if (lane == 0) {
        float di = g_dinv[d];
        float v[7] = {acc.x, acc.y, acc.z, acc.w, hx, hy, hz};
        #pragma unroll
        for (int k = 0; k < 7; ++k) v[k] = fmaf(di, v[k], __ldg(b2 + k));
        float m = v[0];
        #pragma unroll
        for (int k = 1; k < 7; ++k) m = fmaxf(m, v[k]);
        float s = 0.f;
        #pragma unroll
        for (int k = 0; k < 7; ++k) s += expf(v[k] - m);
        float l = m + logf(s);
        float* op = out + (size_t)d * 7;
        #pragma unroll
        for (int k = 0; k < 7; ++k) op[k] = v[k] - l;
    }
}

// ---------------- launch ----------------
extern "C" void kernel_launch(void* const* d_in, const int* in_sizes, int n_in,
                              void* d_out, int out_size)
{
    const float* x  = (const float*)d_in[0];
    const int*   ei = (const int*)d_in[1];     // int32 (JAX x64 disabled)
    const float* W1 = (const float*)d_in[2];
    const float* b1 = (const float*)d_in[3];
    const float* W2 = (const float*)d_in[4];
    const float* b2 = (const float*)d_in[5];

    int n = in_sizes[0] / F_IN;   // 50000
    int E = in_sizes[1] / 2;      // 1600000

    const int smem1 = KPAD * F1 * (int)sizeof(float);   // 92160 B
    cudaFuncSetAttribute(k_gemm1, cudaFuncAttributeMaxDynamicSharedMemorySize, smem1);

    int nb256 = (n + 255) / 256;
    int eb256 = (E + 255) / 256;
    int gwarp = (n + 7) / 8;      // warp-per-node grids (8 warps/block)

    k_init    <<<nb256, 256>>>(n);
    k_count   <<<eb256, 256>>>(ei, E);
    k_alloc   <<<nb256, 256>>>(n);
    k_fill    <<<eb256, 256>>>(ei, E);
    k_gemm1   <<<G1_GRID, G1_BLK, smem1>>>(x, W1, n);
    k_gather16<<<gwarp, 256>>>(b1, n);
    k_layer2  <<<nb256, 256>>>(W2, n);
    k_gather8f<<<gwarp, 256>>>(b2, (float*)d_out, n);
}